// round 1
// baseline (speedup 1.0000x reference)
#include <cuda_runtime.h>

// Problem constants (fixed by the reference): N=100000, E=1600000, H=8, D_IN=128, D_HEAD=16
#define NMAX 100000
#define BR 64          // rows per block in feat kernel
#define WS 144         // padded smem stride for W (128 + 4 pad per 32 cols)
#define XS 132         // padded smem stride for X rows (16B-aligned, bank-spread)

// Scratch (allocation-free rule: __device__ globals)
__device__ float g_feats[NMAX * 128];   // [N, H*D] = [N,128], 51.2 MB (L2-resident)
__device__ float g_f1[NMAX * 8];
__device__ float g_f2[NMAX * 8];

// ---------------------------------------------------------------------------
// Kernel A: feats = x @ Wm  (Wm[d][h*16+o] = W[h][d][o]),
//           f1[n,h] = feats[n,h,:]·a1[h,:] + b1[h], f2 likewise.
// Block = 256 threads, tile = 64 rows x 128 cols, thread tile = 4x8.
// ---------------------------------------------------------------------------
__global__ __launch_bounds__(256) void feat_kernel(
    const float* __restrict__ x, const float* __restrict__ W,
    const float* __restrict__ a1, const float* __restrict__ b1,
    const float* __restrict__ a2, const float* __restrict__ b2,
    int n) {
  extern __shared__ float sm[];
  float* Wsm = sm;              // 128 * WS floats
  float* Xsm = sm + 128 * WS;   // BR * XS floats (reused as feats stash in epilogue)
  const int tid = threadIdx.x;
  const int row0 = blockIdx.x * BR;
  const int nrows = min(BR, n - row0);

  // Rearrange W: Wsm[d][c] with c = h*16+o, 4-word pad every 32 cols
  // (keeps per-thread 8-col float4 pairs 16B-aligned + spreads 16B units
  //  over bank groups -> 2-phase LDS.128, the floor for 16 distinct addrs).
  for (int idx = tid; idx < 128 * 128; idx += 256) {
    int d = idx >> 7, c = idx & 127;
    int h = c >> 4, o = c & 15;
    Wsm[d * WS + c + 4 * (c >> 5)] = W[h * 2048 + d * 16 + o];
  }
  // Stage x tile (float4, padded stride)
  for (int idx = tid; idx < BR * 32; idx += 256) {
    int r = idx >> 5, c4 = idx & 31;
    float4 v = make_float4(0.f, 0.f, 0.f, 0.f);
    if (r < nrows) v = reinterpret_cast<const float4*>(x)[(size_t)(row0 + r) * 32 + c4];
    *reinterpret_cast<float4*>(&Xsm[r * XS + c4 * 4]) = v;
  }
  __syncthreads();

  const int ty = tid >> 4;              // 0..15 -> rows ty*4 .. ty*4+3
  const int tx = tid & 15;              // cols tx*8 .. tx*8+7 (2 half-heads -> contiguous)
  const int c0 = tx * 8;
  const int wbase = c0 + 4 * (tx >> 2); // padded column base

  float acc[4][8];
#pragma unroll
  for (int i = 0; i < 4; i++)
#pragma unroll
    for (int j = 0; j < 8; j++) acc[i][j] = 0.f;

#pragma unroll 4
  for (int d = 0; d < 128; d++) {
    float4 w0 = *reinterpret_cast<const float4*>(&Wsm[d * WS + wbase]);
    float4 w1 = *reinterpret_cast<const float4*>(&Wsm[d * WS + wbase + 4]);
    float wv[8] = {w0.x, w0.y, w0.z, w0.w, w1.x, w1.y, w1.z, w1.w};
#pragma unroll
    for (int i = 0; i < 4; i++) {
      float xv = Xsm[(ty * 4 + i) * XS + d];
#pragma unroll
      for (int j = 0; j < 8; j++) acc[i][j] = fmaf(xv, wv[j], acc[i][j]);
    }
  }

  // Write feats to global (coalesced-ish float4 pairs)
#pragma unroll
  for (int i = 0; i < 4; i++) {
    int r = ty * 4 + i;
    if (r < nrows) {
      float* dp = &g_feats[(size_t)(row0 + r) * 128 + c0];
      *reinterpret_cast<float4*>(dp)     = make_float4(acc[i][0], acc[i][1], acc[i][2], acc[i][3]);
      *reinterpret_cast<float4*>(dp + 4) = make_float4(acc[i][4], acc[i][5], acc[i][6], acc[i][7]);
    }
  }

  // Stash feats tile into Xsm for f1/f2 head reductions
  __syncthreads();
#pragma unroll
  for (int i = 0; i < 4; i++) {
    int r = ty * 4 + i;
#pragma unroll
    for (int j = 0; j < 8; j++) Xsm[r * XS + c0 + j] = acc[i][j];
  }
  __syncthreads();

  // f1/f2: 64 rows x 8 heads, dot over 16 dims
  for (int t = tid; t < BR * 8; t += 256) {
    int r = t >> 3, h = t & 7;
    if (r < nrows) {
      float s1 = __ldg(&b1[h]), s2 = __ldg(&b2[h]);
#pragma unroll
      for (int o = 0; o < 16; o++) {
        float f = Xsm[r * XS + h * 16 + o];
        s1 = fmaf(f, __ldg(&a1[h * 16 + o]), s1);
        s2 = fmaf(f, __ldg(&a2[h * 16 + o]), s2);
      }
      g_f1[(size_t)(row0 + r) * 8 + h] = s1;
      g_f2[(size_t)(row0 + r) * 8 + h] = s2;
    }
  }
}

// ---------------------------------------------------------------------------
// Kernel C: per-source-node edge softmax + weighted gather-sum + ELU.
// One warp per node. src is sorted -> segment via binary search.
// Softmax without max-subtraction (mathematically identical, logits tiny).
// Lane l owns output dims 4l..4l+3 (head = l>>2); lanes 0..7 compute the
// 8 per-head exp weights, broadcast via shfl (MUFU dedup: 8 exps/edge).
// ---------------------------------------------------------------------------
__global__ __launch_bounds__(256) void agg_kernel(
    const int* __restrict__ src, const int* __restrict__ dst,
    float* __restrict__ out, int n, int e_total) {
  int warp = (blockIdx.x * 256 + threadIdx.x) >> 5;
  int lane = threadIdx.x & 31;
  if (warp >= n) return;
  const int node = warp;

  // segment [start, end): lower_bound(node), lower_bound(node+1)
  int lo = 0, hi = e_total;
  while (lo < hi) { int mid = (lo + hi) >> 1; if (__ldg(&src[mid]) < node) lo = mid + 1; else hi = mid; }
  const int start = lo;
  hi = e_total;
  while (lo < hi) { int mid = (lo + hi) >> 1; if (__ldg(&src[mid]) < node + 1) lo = mid + 1; else hi = mid; }
  const int end = lo;

  float4 acc = make_float4(0.f, 0.f, 0.f, 0.f);
  float S = 0.f;
  const float f1i = (lane < 8) ? g_f1[(size_t)node * 8 + lane] : 0.f;
  const float4* feats4 = reinterpret_cast<const float4*>(g_feats);

  for (int e = start; e < end; e++) {
    int d = __ldg(&dst[e]);
    float wv = 0.f;
    if (lane < 8) {
      float z = f1i + g_f2[(size_t)d * 8 + lane];
      z = fmaxf(z, 0.2f * z);       // leaky_relu(0.2)
      wv = __expf(z);
    }
    float w = __shfl_sync(0xffffffffu, wv, lane >> 2);
    float4 f = feats4[(size_t)d * 32 + lane];
    acc.x = fmaf(w, f.x, acc.x);
    acc.y = fmaf(w, f.y, acc.y);
    acc.z = fmaf(w, f.z, acc.z);
    acc.w = fmaf(w, f.w, acc.w);
    S += w;                          // same within each 4-lane head group
  }

  float4 o = make_float4(0.f, 0.f, 0.f, 0.f);
  if (end > start) {
    float inv = 1.f / S;
    o.x = acc.x * inv; o.y = acc.y * inv; o.z = acc.z * inv; o.w = acc.w * inv;
  }
  // ELU (alpha=1)
  o.x = o.x > 0.f ? o.x : expm1f(o.x);
  o.y = o.y > 0.f ? o.y : expm1f(o.y);
  o.z = o.z > 0.f ? o.z : expm1f(o.z);
  o.w = o.w > 0.f ? o.w : expm1f(o.w);
  reinterpret_cast<float4*>(out)[(size_t)node * 32 + lane] = o;
}

// ---------------------------------------------------------------------------
extern "C" void kernel_launch(void* const* d_in, const int* in_sizes, int n_in,
                              void* d_out, int out_size) {
  const float* x  = (const float*)d_in[0];
  const float* W  = (const float*)d_in[1];
  const float* a1 = (const float*)d_in[2];
  const float* b1 = (const float*)d_in[3];
  const float* a2 = (const float*)d_in[4];
  const float* b2 = (const float*)d_in[5];
  const int*  src = (const int*)d_in[6];
  const int*  dst = (const int*)d_in[7];
  float* out = (float*)d_out;

  const int n = in_sizes[0] / 128;   // N
  const int e = in_sizes[6];         // E

  const int smem = (128 * WS + BR * XS) * (int)sizeof(float);  // 107,520 B
  cudaFuncSetAttribute(feat_kernel, cudaFuncAttributeMaxDynamicSharedMemorySize, smem);

  feat_kernel<<<(n + BR - 1) / BR, 256, smem>>>(x, W, a1, b1, a2, b2, n);
  agg_kernel<<<(n + 7) / 8, 256>>>(src, dst, out, n, e);
}

// round 2
// speedup vs baseline: 1.1902x; 1.1902x over previous
#include <cuda_runtime.h>

// Problem constants: N=100000, E=1600000, H=8, D_IN=128, D_HEAD=16
#define NMAX 100000
#define BR 128         // rows per block in feat kernel
#define WS 144         // padded smem stride for W (128 + 4 pad per 32 cols)
#define XS 132         // padded smem stride for X rows

// Scratch (allocation-free rule: __device__ globals)
__device__ float g_feats[NMAX * 128];   // [N,128] 51.2 MB (L2-resident)
__device__ float g_f1[NMAX * 8];
__device__ float g_f2[NMAX * 8];
__device__ int   g_rowptr[NMAX + 1];

// ---------------------------------------------------------------------------
// rowptr: g_rowptr[v] = first edge e with src[e] >= v  (src is sorted)
// ---------------------------------------------------------------------------
__global__ void rowptr_kernel(const int* __restrict__ src, int e_total, int n) {
  int e = blockIdx.x * blockDim.x + threadIdx.x;
  if (e >= e_total) return;
  int s = __ldg(&src[e]);
  int prev = (e == 0) ? -1 : __ldg(&src[e - 1]);
  for (int v = prev + 1; v <= s; v++) g_rowptr[v] = e;
  if (e == e_total - 1)
    for (int v = s + 1; v <= n; v++) g_rowptr[v] = e_total;
}

// ---------------------------------------------------------------------------
// Kernel A: feats = x @ Wm  (Wm[d][h*16+o] = W[h][d][o]) + f1/f2 epilogue.
// 256 threads, tile 128x128, thread tile 8x8, k grouped by 4 (all LDS.128).
// ---------------------------------------------------------------------------
__global__ __launch_bounds__(256) void feat_kernel(
    const float* __restrict__ x, const float* __restrict__ W,
    const float* __restrict__ a1, const float* __restrict__ b1,
    const float* __restrict__ a2, const float* __restrict__ b2,
    int n) {
  extern __shared__ float sm[];
  float* Wsm = sm;              // 128 * WS
  float* Xsm = sm + 128 * WS;   // BR * XS (reused as feats stash in epilogue)
  const int tid = threadIdx.x;
  const int row0 = blockIdx.x * BR;
  const int nrows = min(BR, n - row0);

  // W rearrange: Wsm[d][c], c = h*16+o, +4 pad per 32 cols
  for (int idx = tid; idx < 128 * 128; idx += 256) {
    int d = idx >> 7, c = idx & 127;
    int h = c >> 4, o = c & 15;
    Wsm[d * WS + c + 4 * (c >> 5)] = W[h * 2048 + d * 16 + o];
  }
  // Stage x tile (float4), zero-fill OOB rows
  for (int idx = tid; idx < BR * 32; idx += 256) {
    int r = idx >> 5, c4 = idx & 31;
    float4 v = make_float4(0.f, 0.f, 0.f, 0.f);
    if (r < nrows) v = reinterpret_cast<const float4*>(x)[(size_t)(row0 + r) * 32 + c4];
    *reinterpret_cast<float4*>(&Xsm[r * XS + c4 * 4]) = v;
  }
  __syncthreads();

  const int ty = tid >> 4;              // 0..15 -> rows ty*8 .. ty*8+7
  const int tx = tid & 15;              // cols tx*8 .. tx*8+7
  const int c0 = tx * 8;
  const int wbase = c0 + 4 * (tx >> 2);

  float acc[8][8];
#pragma unroll
  for (int i = 0; i < 8; i++)
#pragma unroll
    for (int j = 0; j < 8; j++) acc[i][j] = 0.f;

#pragma unroll 1
  for (int dk = 0; dk < 128; dk += 4) {
    float4 xv[8];
#pragma unroll
    for (int i = 0; i < 8; i++)
      xv[i] = *reinterpret_cast<const float4*>(&Xsm[(ty * 8 + i) * XS + dk]);
#pragma unroll
    for (int dd = 0; dd < 4; dd++) {
      float4 w0 = *reinterpret_cast<const float4*>(&Wsm[(dk + dd) * WS + wbase]);
      float4 w1 = *reinterpret_cast<const float4*>(&Wsm[(dk + dd) * WS + wbase + 4]);
      float wv[8] = {w0.x, w0.y, w0.z, w0.w, w1.x, w1.y, w1.z, w1.w};
#pragma unroll
      for (int i = 0; i < 8; i++) {
        float xs = (dd == 0) ? xv[i].x : (dd == 1) ? xv[i].y : (dd == 2) ? xv[i].z : xv[i].w;
#pragma unroll
        for (int j = 0; j < 8; j++) acc[i][j] = fmaf(xs, wv[j], acc[i][j]);
      }
    }
  }

  // Write feats
#pragma unroll
  for (int i = 0; i < 8; i++) {
    int r = ty * 8 + i;
    if (r < nrows) {
      float* dp = &g_feats[(size_t)(row0 + r) * 128 + c0];
      *reinterpret_cast<float4*>(dp)     = make_float4(acc[i][0], acc[i][1], acc[i][2], acc[i][3]);
      *reinterpret_cast<float4*>(dp + 4) = make_float4(acc[i][4], acc[i][5], acc[i][6], acc[i][7]);
    }
  }

  // Stash feats tile into Xsm for f1/f2 reductions
  __syncthreads();
#pragma unroll
  for (int i = 0; i < 8; i++) {
    int r = ty * 8 + i;
#pragma unroll
    for (int j = 0; j < 8; j++) Xsm[r * XS + c0 + j] = acc[i][j];
  }
  __syncthreads();

  for (int t = tid; t < BR * 8; t += 256) {
    int r = t >> 3, h = t & 7;
    if (r < nrows) {
      float s1 = __ldg(&b1[h]), s2 = __ldg(&b2[h]);
#pragma unroll
      for (int o = 0; o < 16; o++) {
        float f = Xsm[r * XS + h * 16 + o];
        s1 = fmaf(f, __ldg(&a1[h * 16 + o]), s1);
        s2 = fmaf(f, __ldg(&a2[h * 16 + o]), s2);
      }
      g_f1[(size_t)(row0 + r) * 8 + h] = s1;
      g_f2[(size_t)(row0 + r) * 8 + h] = s2;
    }
  }
}

// ---------------------------------------------------------------------------
// Kernel C: one warp per node; rowptr segment; unroll x4 with batched loads.
// Lane l owns dims 4l..4l+3 (head = l>>2). Each lane computes its own exp
// (4-lane group reads the same f2 word -> 1 sector; removes shfl chain).
// ---------------------------------------------------------------------------
__global__ __launch_bounds__(256) void agg_kernel(
    const int* __restrict__ dst, float* __restrict__ out, int n) {
  int warp = (blockIdx.x * 256 + threadIdx.x) >> 5;
  int lane = threadIdx.x & 31;
  if (warp >= n) return;
  const int node = warp;
  const int h = lane >> 2;

  const int start = g_rowptr[node];
  const int end   = g_rowptr[node + 1];

  const float f1h = g_f1[(size_t)node * 8 + h];
  const float4* feats4 = reinterpret_cast<const float4*>(g_feats);

  float4 acc = make_float4(0.f, 0.f, 0.f, 0.f);
  float S = 0.f;

  int e = start;
  for (; e + 4 <= end; e += 4) {
    int d0 = __ldg(&dst[e]);
    int d1 = __ldg(&dst[e + 1]);
    int d2 = __ldg(&dst[e + 2]);
    int d3 = __ldg(&dst[e + 3]);
    float z0 = f1h + __ldg(&g_f2[(size_t)d0 * 8 + h]);
    float z1 = f1h + __ldg(&g_f2[(size_t)d1 * 8 + h]);
    float z2 = f1h + __ldg(&g_f2[(size_t)d2 * 8 + h]);
    float z3 = f1h + __ldg(&g_f2[(size_t)d3 * 8 + h]);
    float4 q0 = feats4[(size_t)d0 * 32 + lane];
    float4 q1 = feats4[(size_t)d1 * 32 + lane];
    float4 q2 = feats4[(size_t)d2 * 32 + lane];
    float4 q3 = feats4[(size_t)d3 * 32 + lane];
    float w0 = __expf(fmaxf(z0, 0.2f * z0));
    float w1 = __expf(fmaxf(z1, 0.2f * z1));
    float w2 = __expf(fmaxf(z2, 0.2f * z2));
    float w3 = __expf(fmaxf(z3, 0.2f * z3));
    acc.x = fmaf(w0, q0.x, acc.x); acc.y = fmaf(w0, q0.y, acc.y);
    acc.z = fmaf(w0, q0.z, acc.z); acc.w = fmaf(w0, q0.w, acc.w);
    acc.x = fmaf(w1, q1.x, acc.x); acc.y = fmaf(w1, q1.y, acc.y);
    acc.z = fmaf(w1, q1.z, acc.z); acc.w = fmaf(w1, q1.w, acc.w);
    acc.x = fmaf(w2, q2.x, acc.x); acc.y = fmaf(w2, q2.y, acc.y);
    acc.z = fmaf(w2, q2.z, acc.z); acc.w = fmaf(w2, q2.w, acc.w);
    acc.x = fmaf(w3, q3.x, acc.x); acc.y = fmaf(w3, q3.y, acc.y);
    acc.z = fmaf(w3, q3.z, acc.z); acc.w = fmaf(w3, q3.w, acc.w);
    S += (w0 + w1) + (w2 + w3);
  }
  for (; e < end; e++) {
    int d = __ldg(&dst[e]);
    float z = f1h + __ldg(&g_f2[(size_t)d * 8 + h]);
    float w = __expf(fmaxf(z, 0.2f * z));
    float4 q = feats4[(size_t)d * 32 + lane];
    acc.x = fmaf(w, q.x, acc.x); acc.y = fmaf(w, q.y, acc.y);
    acc.z = fmaf(w, q.z, acc.z); acc.w = fmaf(w, q.w, acc.w);
    S += w;
  }

  float4 o = make_float4(0.f, 0.f, 0.f, 0.f);
  if (end > start) {
    float inv = 1.f / S;
    o.x = acc.x * inv; o.y = acc.y * inv; o.z = acc.z * inv; o.w = acc.w * inv;
  }
  o.x = o.x > 0.f ? o.x : expm1f(o.x);
  o.y = o.y > 0.f ? o.y : expm1f(o.y);
  o.z = o.z > 0.f ? o.z : expm1f(o.z);
  o.w = o.w > 0.f ? o.w : expm1f(o.w);
  reinterpret_cast<float4*>(out)[(size_t)node * 32 + lane] = o;
}

// ---------------------------------------------------------------------------
extern "C" void kernel_launch(void* const* d_in, const int* in_sizes, int n_in,
                              void* d_out, int out_size) {
  const float* x  = (const float*)d_in[0];
  const float* W  = (const float*)d_in[1];
  const float* a1 = (const float*)d_in[2];
  const float* b1 = (const float*)d_in[3];
  const float* a2 = (const float*)d_in[4];
  const float* b2 = (const float*)d_in[5];
  const int*  src = (const int*)d_in[6];
  const int*  dst = (const int*)d_in[7];
  float* out = (float*)d_out;

  const int n = in_sizes[0] / 128;   // N
  const int e = in_sizes[6];         // E

  const int smem = (128 * WS + BR * XS) * (int)sizeof(float);  // 141,312 B
  cudaFuncSetAttribute(feat_kernel, cudaFuncAttributeMaxDynamicSharedMemorySize, smem);

  rowptr_kernel<<<(e + 255) / 256, 256>>>(src, e, n);
  feat_kernel<<<(n + BR - 1) / BR, 256, smem>>>(x, W, a1, b1, a2, b2, n);
  agg_kernel<<<(n + 7) / 8, 256>>>(dst, out, n);
}

// round 4
// speedup vs baseline: 1.4867x; 1.2491x over previous
#include <cuda_runtime.h>
#include <cuda_fp16.h>
#include <cstdint>

// Problem constants: N=100000, E=1600000, H=8, D_IN=128, D_HEAD=16
#define NMAX 100000

// Scratch (allocation-free rule: __device__ globals)
__device__ __half g_feats_h[NMAX * 128];  // [N,128] fp16, 25.6 MB (L2-resident)
__device__ float  g_f1[NMAX * 8];
__device__ float  g_f2[NMAX * 8];
__device__ int    g_rowptr[NMAX + 1];

__device__ __forceinline__ uint32_t f2tf32(float f) {
  uint32_t u; asm("cvt.rna.tf32.f32 %0, %1;" : "=r"(u) : "f"(f)); return u;
}
__device__ __forceinline__ void mma_tf32(float c[4], uint32_t a0, uint32_t a1,
                                         uint32_t a2, uint32_t a3,
                                         uint32_t b0, uint32_t b1) {
  asm volatile(
      "mma.sync.aligned.m16n8k8.row.col.f32.tf32.tf32.f32 "
      "{%0,%1,%2,%3}, {%4,%5,%6,%7}, {%8,%9}, {%0,%1,%2,%3};"
      : "+f"(c[0]), "+f"(c[1]), "+f"(c[2]), "+f"(c[3])
      : "r"(a0), "r"(a1), "r"(a2), "r"(a3), "r"(b0), "r"(b1));
}

// ---------------------------------------------------------------------------
// rowptr: g_rowptr[v] = first edge e with src[e] >= v (src sorted)
// ---------------------------------------------------------------------------
__global__ void rowptr_kernel(const int* __restrict__ src, int e_total, int n) {
  int e = blockIdx.x * blockDim.x + threadIdx.x;
  if (e >= e_total) return;
  int s = __ldg(&src[e]);
  int prev = (e == 0) ? -1 : __ldg(&src[e - 1]);
  for (int v = prev + 1; v <= s; v++) g_rowptr[v] = e;
  if (e == e_total - 1)
    for (int v = s + 1; v <= n; v++) g_rowptr[v] = e_total;
}

// ---------------------------------------------------------------------------
// feat_mma: feats = x @ Wm via mma.sync tf32 (HMMA tensor pipe).
// CTA = 256 thr (8 warps), tile 128 rows x 128 cols, k = 128.
// Warp w: rows w*16..w*16+15, all 128 cols (16 n-tiles of 8).
// Smem: As[128][132] fp32(tf32 bits), Bs[128][136] (Bs[k][n], n = h*16+o).
// Epilogue: C frags -> Eh fp16 smem (overlaps As) -> coalesced feats store
//           + f1/f2 head dots.
// ---------------------------------------------------------------------------
#define AS_STRIDE 132
#define BS_STRIDE 136
#define EH_STRIDE 136
#define SMEM_FEAT_TOTAL (128 * AS_STRIDE * 4 + 128 * BS_STRIDE * 4)  // 137,216 B

__global__ __launch_bounds__(256) void feat_mma_kernel(
    const float* __restrict__ x, const float* __restrict__ W,
    const float* __restrict__ a1, const float* __restrict__ b1,
    const float* __restrict__ a2, const float* __restrict__ b2,
    int n) {
  extern __shared__ char smem[];
  uint32_t* As = reinterpret_cast<uint32_t*>(smem);
  uint32_t* Bs = As + 128 * AS_STRIDE;
  __half*   Eh = reinterpret_cast<__half*>(smem);   // overlaps As (after sync)

  const int tid = threadIdx.x;
  const int w   = tid >> 5;
  const int lane = tid & 31;
  const int qid = lane >> 2;      // 0..7
  const int tq  = lane & 3;       // 0..3
  const int row0 = blockIdx.x * 128;
  const int nrows = min(128, n - row0);

  // Stage A = x tile (tf32-rounded), zero-fill OOB rows
  for (int i = tid; i < 4096; i += 256) {
    int r = i >> 5, k4 = i & 31;
    float4 v = make_float4(0.f, 0.f, 0.f, 0.f);
    if (r < nrows) v = reinterpret_cast<const float4*>(x)[(size_t)(row0 + r) * 32 + k4];
    uint4 u = make_uint4(f2tf32(v.x), f2tf32(v.y), f2tf32(v.z), f2tf32(v.w));
    *reinterpret_cast<uint4*>(&As[r * AS_STRIDE + k4 * 4]) = u;
  }
  // Stage B: Bs[k=d][n=h*16+o] = W[h][d][o] (tf32-rounded), coalesced reads
  for (int i = tid; i < 4096; i += 256) {
    int h = i >> 9, d = (i >> 2) & 127, o0 = (i & 3) * 4;
    float4 v = *reinterpret_cast<const float4*>(&W[(size_t)h * 2048 + d * 16 + o0]);
    uint4 u = make_uint4(f2tf32(v.x), f2tf32(v.y), f2tf32(v.z), f2tf32(v.w));
    *reinterpret_cast<uint4*>(&Bs[d * BS_STRIDE + h * 16 + o0]) = u;
  }
  __syncthreads();

  float c[16][4];
#pragma unroll
  for (int nt = 0; nt < 16; nt++)
#pragma unroll
    for (int j = 0; j < 4; j++) c[nt][j] = 0.f;

  const uint32_t* Abase = &As[(w * 16 + qid) * AS_STRIDE + tq];
#pragma unroll 4
  for (int ks = 0; ks < 16; ks++) {
    const int k0 = ks * 8;
    uint32_t a0 = Abase[k0];
    uint32_t a2 = Abase[k0 + 4];
    uint32_t a1 = Abase[k0 + 8 * AS_STRIDE];
    uint32_t a3 = Abase[k0 + 8 * AS_STRIDE + 4];
    const uint32_t* B0 = &Bs[(k0 + tq) * BS_STRIDE + qid];
    const uint32_t* B1 = B0 + 4 * BS_STRIDE;
#pragma unroll
    for (int nt = 0; nt < 16; nt++)
      mma_tf32(c[nt], a0, a1, a2, a3, B0[nt * 8], B1[nt * 8]);
  }

  __syncthreads();  // done reading As/Bs; reuse As region as Eh

  // C frags -> Eh[row][col] fp16 (stride 136 halves: conflict-free)
  {
    const int r0 = w * 16 + qid;
#pragma unroll
    for (int nt = 0; nt < 16; nt++) {
      int col = nt * 8 + tq * 2;
      *reinterpret_cast<__half2*>(&Eh[r0 * EH_STRIDE + col]) =
          __floats2half2_rn(c[nt][0], c[nt][1]);
      *reinterpret_cast<__half2*>(&Eh[(r0 + 8) * EH_STRIDE + col]) =
          __floats2half2_rn(c[nt][2], c[nt][3]);
    }
  }
  __syncthreads();

  // Coalesced feats store: 128 rows x 16 uint4 (8 halves each)
  for (int task = tid; task < 2048; task += 256) {
    int r = task >> 4, seg = task & 15;
    if (r < nrows)
      *reinterpret_cast<uint4*>(&g_feats_h[(size_t)(row0 + r) * 128 + seg * 8]) =
          *reinterpret_cast<const uint4*>(&Eh[r * EH_STRIDE + seg * 8]);
  }
  // f1/f2: 128 rows x 8 heads, dot over 16 dims (fp32 math on fp16 feats)
  for (int task = tid; task < 1024; task += 256) {
    int r = task >> 3, h = task & 7;
    if (r < nrows) {
      float s1 = __ldg(&b1[h]), s2 = __ldg(&b2[h]);
#pragma unroll
      for (int o = 0; o < 16; o++) {
        float f = __half2float(Eh[r * EH_STRIDE + h * 16 + o]);
        s1 = fmaf(f, __ldg(&a1[h * 16 + o]), s1);
        s2 = fmaf(f, __ldg(&a2[h * 16 + o]), s2);
      }
      g_f1[(size_t)(row0 + r) * 8 + h] = s1;
      g_f2[(size_t)(row0 + r) * 8 + h] = s2;
    }
  }
}

// ---------------------------------------------------------------------------
// agg: one warp per node. Per 4-edge group, lane l computes ONE exp
// (edge l>>3, head l&7) -> 8 exps/edge; weights distributed by shfl.
// feats gathered as fp16 (uint2 = 4 dims per lane).
// ---------------------------------------------------------------------------
__global__ __launch_bounds__(256) void agg_kernel(
    const int* __restrict__ dst, float* __restrict__ out, int n) {
  int warp = (blockIdx.x * 256 + threadIdx.x) >> 5;
  int lane = threadIdx.x & 31;
  if (warp >= n) return;
  const int node = warp;
  const int h4 = lane >> 2;   // head this lane accumulates (4 dims)
  const int h8 = lane & 7;    // head for this lane's exp duty
  const int j8 = lane >> 3;   // edge slot (0..3) for exp duty

  const int start = g_rowptr[node];
  const int end   = g_rowptr[node + 1];
  const float f1e = g_f1[(size_t)node * 8 + h8];
  const uint2* fh = reinterpret_cast<const uint2*>(g_feats_h);

  float4 acc = make_float4(0.f, 0.f, 0.f, 0.f);
  float S = 0.f;

  int e = start;
  for (; e + 4 <= end; e += 4) {
    int dme = __ldg(&dst[e + j8]);
    float z = f1e + __ldg(&g_f2[(size_t)dme * 8 + h8]);
    float wme = __expf(fmaxf(z, 0.2f * z));
#pragma unroll
    for (int j = 0; j < 4; j++) {
      int dj = __ldg(&dst[e + j]);                       // warp-uniform, L1-hot
      float wj = __shfl_sync(0xffffffffu, wme, j * 8 + h4);
      uint2 q = __ldg(&fh[(size_t)dj * 32 + lane]);
      float2 fa = __half22float2(*reinterpret_cast<__half2*>(&q.x));
      float2 fb = __half22float2(*reinterpret_cast<__half2*>(&q.y));
      acc.x = fmaf(wj, fa.x, acc.x); acc.y = fmaf(wj, fa.y, acc.y);
      acc.z = fmaf(wj, fb.x, acc.z); acc.w = fmaf(wj, fb.y, acc.w);
      S += wj;
    }
  }
  for (; e < end; e++) {
    int d = __ldg(&dst[e]);
    float wv = 0.f;
    if (lane < 8) {
      float z = f1e + __ldg(&g_f2[(size_t)d * 8 + lane]);
      wv = __expf(fmaxf(z, 0.2f * z));
    }
    float w = __shfl_sync(0xffffffffu, wv, h4);
    uint2 q = __ldg(&fh[(size_t)d * 32 + lane]);
    float2 fa = __half22float2(*reinterpret_cast<__half2*>(&q.x));
    float2 fb = __half22float2(*reinterpret_cast<__half2*>(&q.y));
    acc.x = fmaf(w, fa.x, acc.x); acc.y = fmaf(w, fa.y, acc.y);
    acc.z = fmaf(w, fb.x, acc.z); acc.w = fmaf(w, fb.y, acc.w);
    S += w;
  }

  float4 o = make_float4(0.f, 0.f, 0.f, 0.f);
  if (end > start) {
    float inv = 1.f / S;
    o.x = acc.x * inv; o.y = acc.y * inv; o.z = acc.z * inv; o.w = acc.w * inv;
  }
  o.x = o.x > 0.f ? o.x : expm1f(o.x);
  o.y = o.y > 0.f ? o.y : expm1f(o.y);
  o.z = o.z > 0.f ? o.z : expm1f(o.z);
  o.w = o.w > 0.f ? o.w : expm1f(o.w);
  reinterpret_cast<float4*>(out)[(size_t)node * 32 + lane] = o;
}

// ---------------------------------------------------------------------------
extern "C" void kernel_launch(void* const* d_in, const int* in_sizes, int n_in,
                              void* d_out, int out_size) {
  const float* x  = (const float*)d_in[0];
  const float* W  = (const float*)d_in[1];
  const float* a1 = (const float*)d_in[2];
  const float* b1 = (const float*)d_in[3];
  const float* a2 = (const float*)d_in[4];
  const float* b2 = (const float*)d_in[5];
  const int*  src = (const int*)d_in[6];
  const int*  dst = (const int*)d_in[7];
  float* out = (float*)d_out;

  const int n = in_sizes[0] / 128;   // N
  const int e = in_sizes[6];         // E

  cudaFuncSetAttribute(feat_mma_kernel, cudaFuncAttributeMaxDynamicSharedMemorySize,
                       SMEM_FEAT_TOTAL);

  rowptr_kernel<<<(e + 255) / 256, 256>>>(src, e, n);
  feat_mma_kernel<<<(n + 127) / 128, 256, SMEM_FEAT_TOTAL>>>(x, W, a1, b1, a2, b2, n);
  agg_kernel<<<(n + 7) / 8, 256>>>(dst, out, n);
}

// round 5
// speedup vs baseline: 1.8792x; 1.2640x over previous
#include <cuda_runtime.h>
#include <cuda_fp16.h>
#include <cstdint>

// Problem constants: N=100000, E=1600000, H=8, D_IN=128, D_HEAD=16
#define NMAX 100000

// Scratch (allocation-free rule: __device__ globals)
__device__ __half g_feats_h[NMAX * 128];  // [N,128] fp16, 25.6 MB (L2-resident)
__device__ float  g_f1[NMAX * 8];
__device__ float  g_f2[NMAX * 8];
__device__ int    g_rowptr[NMAX + 1];

__device__ __forceinline__ uint32_t f2tf32(float f) {
  uint32_t u; asm("cvt.rna.tf32.f32 %0, %1;" : "=r"(u) : "f"(f)); return u;
}
__device__ __forceinline__ void mma_tf32(float c[4], uint32_t a0, uint32_t a1,
                                         uint32_t a2, uint32_t a3,
                                         uint32_t b0, uint32_t b1) {
  asm volatile(
      "mma.sync.aligned.m16n8k8.row.col.f32.tf32.tf32.f32 "
      "{%0,%1,%2,%3}, {%4,%5,%6,%7}, {%8,%9}, {%0,%1,%2,%3};"
      : "+f"(c[0]), "+f"(c[1]), "+f"(c[2]), "+f"(c[3])
      : "r"(a0), "r"(a1), "r"(a2), "r"(a3), "r"(b0), "r"(b1));
}

// ---------------------------------------------------------------------------
// rowptr: g_rowptr[v] = first edge e with src[e] >= v (src sorted).
// prev fetched via shfl_up (lane 0 reloads) -> ~half the read traffic.
// ---------------------------------------------------------------------------
__global__ void rowptr_kernel(const int* __restrict__ src, int e_total, int n) {
  int e = blockIdx.x * blockDim.x + threadIdx.x;
  int ee = min(e, e_total - 1);
  int s = __ldg(&src[ee]);
  int lane = threadIdx.x & 31;
  int prev = __shfl_up_sync(0xffffffffu, s, 1);
  if (lane == 0) prev = (ee == 0) ? -1 : __ldg(&src[ee - 1]);
  if (e >= e_total) return;
  for (int v = prev + 1; v <= s; v++) g_rowptr[v] = e;
  if (e == e_total - 1)
    for (int v = s + 1; v <= n; v++) g_rowptr[v] = e_total;
}

// ---------------------------------------------------------------------------
// feat_mma: feats = x @ Wm via mma.sync tf32. CTA = 256 thr (8 warps),
// tile 64 rows x 128 cols, k = 128. smem 103KB -> 2 CTA/SM (16 warps).
// Warp w: rows (w&3)*16..+15, cols (w>>2)*64..+63 (8 n-tiles of 8).
// ---------------------------------------------------------------------------
#define AS_STRIDE 132
#define BS_STRIDE 136
#define EH_STRIDE 136
#define SMEM_FEAT_TOTAL ((64 * AS_STRIDE + 128 * BS_STRIDE) * 4)  // 103,424 B

__global__ __launch_bounds__(256, 2) void feat_mma_kernel(
    const float* __restrict__ x, const float* __restrict__ W,
    const float* __restrict__ a1, const float* __restrict__ b1,
    const float* __restrict__ a2, const float* __restrict__ b2,
    int n) {
  extern __shared__ char smem[];
  uint32_t* As = reinterpret_cast<uint32_t*>(smem);
  uint32_t* Bs = As + 64 * AS_STRIDE;
  __half*   Eh = reinterpret_cast<__half*>(smem);   // overlays As after sync

  const int tid = threadIdx.x;
  const int w    = tid >> 5;
  const int lane = tid & 31;
  const int qid = lane >> 2;      // 0..7
  const int tq  = lane & 3;       // 0..3
  const int row0 = blockIdx.x * 64;
  const int nrows = min(64, n - row0);

  // Stage A = x tile (tf32-rounded), zero-fill OOB rows
  for (int i = tid; i < 2048; i += 256) {
    int r = i >> 5, k4 = i & 31;
    float4 v = make_float4(0.f, 0.f, 0.f, 0.f);
    if (r < nrows) v = reinterpret_cast<const float4*>(x)[(size_t)(row0 + r) * 32 + k4];
    uint4 u = make_uint4(f2tf32(v.x), f2tf32(v.y), f2tf32(v.z), f2tf32(v.w));
    *reinterpret_cast<uint4*>(&As[r * AS_STRIDE + k4 * 4]) = u;
  }
  // Stage B: Bs[k=d][n=h*16+o] = W[h][d][o] (tf32-rounded)
  for (int i = tid; i < 4096; i += 256) {
    int h = i >> 9, d = (i >> 2) & 127, o0 = (i & 3) * 4;
    float4 v = *reinterpret_cast<const float4*>(&W[(size_t)h * 2048 + d * 16 + o0]);
    uint4 u = make_uint4(f2tf32(v.x), f2tf32(v.y), f2tf32(v.z), f2tf32(v.w));
    *reinterpret_cast<uint4*>(&Bs[d * BS_STRIDE + h * 16 + o0]) = u;
  }
  __syncthreads();

  const int rw = (w & 3) * 16;     // warp row base
  const int cb = (w >> 2) * 64;    // warp col base

  float c[8][4];
#pragma unroll
  for (int nt = 0; nt < 8; nt++)
#pragma unroll
    for (int j = 0; j < 4; j++) c[nt][j] = 0.f;

  const uint32_t* Abase = &As[(rw + qid) * AS_STRIDE + tq];
#pragma unroll 4
  for (int ks = 0; ks < 16; ks++) {
    const int k0 = ks * 8;
    uint32_t a0 = Abase[k0];
    uint32_t a2 = Abase[k0 + 4];
    uint32_t a1 = Abase[k0 + 8 * AS_STRIDE];
    uint32_t a3 = Abase[k0 + 8 * AS_STRIDE + 4];
    const uint32_t* B0 = &Bs[(k0 + tq) * BS_STRIDE + cb + qid];
    const uint32_t* B1 = B0 + 4 * BS_STRIDE;
#pragma unroll
    for (int nt = 0; nt < 8; nt++)
      mma_tf32(c[nt], a0, a1, a2, a3, B0[nt * 8], B1[nt * 8]);
  }

  __syncthreads();  // done reading As; overlay Eh

  // C frags -> Eh[row][col] fp16
  {
    const int r0 = rw + qid;
#pragma unroll
    for (int nt = 0; nt < 8; nt++) {
      int col = cb + nt * 8 + tq * 2;
      *reinterpret_cast<__half2*>(&Eh[r0 * EH_STRIDE + col]) =
          __floats2half2_rn(c[nt][0], c[nt][1]);
      *reinterpret_cast<__half2*>(&Eh[(r0 + 8) * EH_STRIDE + col]) =
          __floats2half2_rn(c[nt][2], c[nt][3]);
    }
  }
  __syncthreads();

  // Coalesced feats store: 64 rows x 16 uint4 (8 halves each)
  for (int task = tid; task < 1024; task += 256) {
    int r = task >> 4, seg = task & 15;
    if (r < nrows)
      *reinterpret_cast<uint4*>(&g_feats_h[(size_t)(row0 + r) * 128 + seg * 8]) =
          *reinterpret_cast<const uint4*>(&Eh[r * EH_STRIDE + seg * 8]);
  }
  // f1/f2: 64 rows x 8 heads, dot over 16 dims
  for (int task = tid; task < 512; task += 256) {
    int r = task >> 3, h = task & 7;
    if (r < nrows) {
      float s1 = __ldg(&b1[h]), s2 = __ldg(&b2[h]);
#pragma unroll
      for (int o = 0; o < 16; o++) {
        float f = __half2float(Eh[r * EH_STRIDE + h * 16 + o]);
        s1 = fmaf(f, __ldg(&a1[h * 16 + o]), s1);
        s2 = fmaf(f, __ldg(&a2[h * 16 + o]), s2);
      }
      g_f1[(size_t)(row0 + r) * 8 + h] = s1;
      g_f2[(size_t)(row0 + r) * 8 + h] = s2;
    }
  }
}

// ---------------------------------------------------------------------------
// agg: one warp per node. All-lane exp (1 MUFU instr/edge, never binding),
// unroll x8 -> 16 independent gathers in flight. fp16 feats (uint2/lane).
// ---------------------------------------------------------------------------
__global__ __launch_bounds__(256) void agg_kernel(
    const int* __restrict__ dst, float* __restrict__ out, int n) {
  int warp = (blockIdx.x * 256 + threadIdx.x) >> 5;
  int lane = threadIdx.x & 31;
  if (warp >= n) return;
  const int node = warp;
  const int h4 = lane >> 2;   // head this lane accumulates (4 dims)

  const int start = g_rowptr[node];
  const int end   = g_rowptr[node + 1];
  const float f1h = g_f1[(size_t)node * 8 + h4];
  const uint2* fh = reinterpret_cast<const uint2*>(g_feats_h);

  float4 acc = make_float4(0.f, 0.f, 0.f, 0.f);
  float S = 0.f;

  int e = start;
  for (; e + 8 <= end; e += 8) {
    int d[8];
#pragma unroll
    for (int j = 0; j < 8; j++) d[j] = __ldg(&dst[e + j]);
    float z[8];
#pragma unroll
    for (int j = 0; j < 8; j++) z[j] = f1h + __ldg(&g_f2[(size_t)d[j] * 8 + h4]);
    uint2 q[8];
#pragma unroll
    for (int j = 0; j < 8; j++) q[j] = __ldg(&fh[(size_t)d[j] * 32 + lane]);
#pragma unroll
    for (int j = 0; j < 8; j++) {
      float wj = __expf(fmaxf(z[j], 0.2f * z[j]));
      float2 fa = __half22float2(*reinterpret_cast<__half2*>(&q[j].x));
      float2 fb = __half22float2(*reinterpret_cast<__half2*>(&q[j].y));
      acc.x = fmaf(wj, fa.x, acc.x); acc.y = fmaf(wj, fa.y, acc.y);
      acc.z = fmaf(wj, fb.x, acc.z); acc.w = fmaf(wj, fb.y, acc.w);
      S += wj;
    }
  }
  for (; e < end; e++) {
    int dj = __ldg(&dst[e]);
    float zj = f1h + __ldg(&g_f2[(size_t)dj * 8 + h4]);
    float wj = __expf(fmaxf(zj, 0.2f * zj));
    uint2 qj = __ldg(&fh[(size_t)dj * 32 + lane]);
    float2 fa = __half22float2(*reinterpret_cast<__half2*>(&qj.x));
    float2 fb = __half22float2(*reinterpret_cast<__half2*>(&qj.y));
    acc.x = fmaf(wj, fa.x, acc.x); acc.y = fmaf(wj, fa.y, acc.y);
    acc.z = fmaf(wj, fb.x, acc.z); acc.w = fmaf(wj, fb.y, acc.w);
    S += wj;
  }

  float4 o = make_float4(0.f, 0.f, 0.f, 0.f);
  if (end > start) {
    float inv = 1.f / S;
    o.x = acc.x * inv; o.y = acc.y * inv; o.z = acc.z * inv; o.w = acc.w * inv;
  }
  o.x = o.x > 0.f ? o.x : expm1f(o.x);
  o.y = o.y > 0.f ? o.y : expm1f(o.y);
  o.z = o.z > 0.f ? o.z : expm1f(o.z);
  o.w = o.w > 0.f ? o.w : expm1f(o.w);
  reinterpret_cast<float4*>(out)[(size_t)node * 32 + lane] = o;
}

// ---------------------------------------------------------------------------
extern "C" void kernel_launch(void* const* d_in, const int* in_sizes, int n_in,
                              void* d_out, int out_size) {
  const float* x  = (const float*)d_in[0];
  const float* W  = (const float*)d_in[1];
  const float* a1 = (const float*)d_in[2];
  const float* b1 = (const float*)d_in[3];
  const float* a2 = (const float*)d_in[4];
  const float* b2 = (const float*)d_in[5];
  const int*  src = (const int*)d_in[6];
  const int*  dst = (const int*)d_in[7];
  float* out = (float*)d_out;

  const int n = in_sizes[0] / 128;   // N
  const int e = in_sizes[6];         // E

  cudaFuncSetAttribute(feat_mma_kernel, cudaFuncAttributeMaxDynamicSharedMemorySize,
                       SMEM_FEAT_TOTAL);

  rowptr_kernel<<<(e + 255) / 256, 256>>>(src, e, n);
  feat_mma_kernel<<<(n + 63) / 64, 256, SMEM_FEAT_TOTAL>>>(x, W, a1, b1, a2, b2, n);
  agg_kernel<<<(n + 7) / 8, 256>>>(dst, out, n);
}

// round 6
// speedup vs baseline: 2.0859x; 1.1100x over previous
#include <cuda_runtime.h>
#include <cuda_fp16.h>
#include <cstdint>

// Problem constants: N=100000, E=1600000, H=8, D_IN=128, D_HEAD=16
#define NMAX 100000
#define FEAT_CTAS 296   // 2 per SM on 148 SMs

// Scratch (allocation-free rule: __device__ globals)
__device__ __half g_feats_h[NMAX * 128];  // [N,128] fp16, 25.6 MB (L2-resident)
__device__ float  g_f1[NMAX * 8];
__device__ float  g_f2[NMAX * 8];
__device__ int    g_rowptr[NMAX + 1];

__device__ __forceinline__ uint32_t f2tf32(float f) {
  uint32_t u; asm("cvt.rna.tf32.f32 %0, %1;" : "=r"(u) : "f"(f)); return u;
}
__device__ __forceinline__ void mma_tf32(float c[4], uint32_t a0, uint32_t a1,
                                         uint32_t a2, uint32_t a3,
                                         uint32_t b0, uint32_t b1) {
  asm volatile(
      "mma.sync.aligned.m16n8k8.row.col.f32.tf32.tf32.f32 "
      "{%0,%1,%2,%3}, {%4,%5,%6,%7}, {%8,%9}, {%0,%1,%2,%3};"
      : "+f"(c[0]), "+f"(c[1]), "+f"(c[2]), "+f"(c[3])
      : "r"(a0), "r"(a1), "r"(a2), "r"(a3), "r"(b0), "r"(b1));
}

// ---------------------------------------------------------------------------
// Fused kernel: blocks [0, rp_blocks) build rowptr (int4, 4 edges/thread);
// blocks [rp_blocks, rp_blocks+feat_ctas) are persistent feat CTAs:
// stage W (B matrix) into smem ONCE, loop over 64-row x-tiles.
// ---------------------------------------------------------------------------
#define AS_STRIDE 132
#define BS_STRIDE 136
#define EH_STRIDE 136
#define SMEM_FEAT_TOTAL ((64 * AS_STRIDE + 128 * BS_STRIDE) * 4)  // 103,424 B

__global__ __launch_bounds__(256, 2) void feat_rp_kernel(
    const float* __restrict__ x, const float* __restrict__ W,
    const float* __restrict__ a1, const float* __restrict__ b1,
    const float* __restrict__ a2, const float* __restrict__ b2,
    const int* __restrict__ src,
    int n, int e_total, int rp_blocks, int n_tiles, int feat_ctas) {
  extern __shared__ char smem[];
  const int tid = threadIdx.x;

  // ---------------- rowptr role ----------------
  if ((int)blockIdx.x < rp_blocks) {
    int base = (blockIdx.x * 256 + tid) * 4;
    if (base < e_total) {
      int cnt = min(4, e_total - base);
      int s[4];
      if (cnt == 4) {
        int4 s4 = *reinterpret_cast<const int4*>(&src[base]);
        s[0] = s4.x; s[1] = s4.y; s[2] = s4.z; s[3] = s4.w;
      } else {
        for (int j = 0; j < cnt; j++) s[j] = __ldg(&src[base + j]);
      }
      int prev = (base == 0) ? -1 : __ldg(&src[base - 1]);
      for (int j = 0; j < cnt; j++) {
        for (int v = prev + 1; v <= s[j]; v++) g_rowptr[v] = base + j;
        prev = s[j];
      }
      if (base + cnt == e_total)
        for (int v = prev + 1; v <= n; v++) g_rowptr[v] = e_total;
    }
    return;
  }

  // ---------------- persistent feat role ----------------
  uint32_t* As = reinterpret_cast<uint32_t*>(smem);
  uint32_t* Bs = As + 64 * AS_STRIDE;
  __half*   Eh = reinterpret_cast<__half*>(smem);   // overlays As between syncs

  const int f    = blockIdx.x - rp_blocks;
  const int w    = tid >> 5;
  const int lane = tid & 31;
  const int qid  = lane >> 2;     // 0..7
  const int tq   = lane & 3;      // 0..3
  const int rw   = (w & 3) * 16;  // warp row base
  const int cb   = (w >> 2) * 64; // warp col base

  // Stage B once: Bs[k=d][nc=h*16+o] = W[h][d][o] (tf32-rounded)
  for (int i = tid; i < 4096; i += 256) {
    int h = i >> 9, d = (i >> 2) & 127, o0 = (i & 3) * 4;
    float4 v = *reinterpret_cast<const float4*>(&W[(size_t)h * 2048 + d * 16 + o0]);
    uint4 u = make_uint4(f2tf32(v.x), f2tf32(v.y), f2tf32(v.z), f2tf32(v.w));
    *reinterpret_cast<uint4*>(&Bs[d * BS_STRIDE + h * 16 + o0]) = u;
  }

  for (int t = f; t < n_tiles; t += feat_ctas) {
    const int row0 = t * 64;
    const int nrows = min(64, n - row0);

    // Stage A tile (tf32-rounded), zero-fill OOB rows
    for (int i = tid; i < 2048; i += 256) {
      int r = i >> 5, k4 = i & 31;
      float4 v = make_float4(0.f, 0.f, 0.f, 0.f);
      if (r < nrows) v = reinterpret_cast<const float4*>(x)[(size_t)(row0 + r) * 32 + k4];
      uint4 u = make_uint4(f2tf32(v.x), f2tf32(v.y), f2tf32(v.z), f2tf32(v.w));
      *reinterpret_cast<uint4*>(&As[r * AS_STRIDE + k4 * 4]) = u;
    }
    __syncthreads();

    float c[8][4];
#pragma unroll
    for (int nt = 0; nt < 8; nt++)
#pragma unroll
      for (int j = 0; j < 4; j++) c[nt][j] = 0.f;

    const uint32_t* Abase = &As[(rw + qid) * AS_STRIDE + tq];
#pragma unroll 4
    for (int ks = 0; ks < 16; ks++) {
      const int k0 = ks * 8;
      uint32_t a0 = Abase[k0];
      uint32_t a2 = Abase[k0 + 4];
      uint32_t a1 = Abase[k0 + 8 * AS_STRIDE];
      uint32_t a3 = Abase[k0 + 8 * AS_STRIDE + 4];
      const uint32_t* B0 = &Bs[(k0 + tq) * BS_STRIDE + cb + qid];
      const uint32_t* B1 = B0 + 4 * BS_STRIDE;
#pragma unroll
      for (int nt = 0; nt < 8; nt++)
        mma_tf32(c[nt], a0, a1, a2, a3, B0[nt * 8], B1[nt * 8]);
    }
    __syncthreads();  // MMA reads of As done; overlay Eh

    // C frags -> Eh[row][col] fp16
    {
      const int r0 = rw + qid;
#pragma unroll
      for (int nt = 0; nt < 8; nt++) {
        int col = cb + nt * 8 + tq * 2;
        *reinterpret_cast<__half2*>(&Eh[r0 * EH_STRIDE + col]) =
            __floats2half2_rn(c[nt][0], c[nt][1]);
        *reinterpret_cast<__half2*>(&Eh[(r0 + 8) * EH_STRIDE + col]) =
            __floats2half2_rn(c[nt][2], c[nt][3]);
      }
    }
    __syncthreads();

    // Coalesced feats store: 64 rows x 16 uint4
    for (int task = tid; task < 1024; task += 256) {
      int r = task >> 4, seg = task & 15;
      if (r < nrows)
        *reinterpret_cast<uint4*>(&g_feats_h[(size_t)(row0 + r) * 128 + seg * 8]) =
            *reinterpret_cast<const uint4*>(&Eh[r * EH_STRIDE + seg * 8]);
    }
    // f1/f2: 64 rows x 8 heads, dot over 16 dims
    for (int task = tid; task < 512; task += 256) {
      int r = task >> 3, h = task & 7;
      if (r < nrows) {
        float s1 = __ldg(&b1[h]), s2 = __ldg(&b2[h]);
#pragma unroll
        for (int o = 0; o < 16; o++) {
          float fv = __half2float(Eh[r * EH_STRIDE + h * 16 + o]);
          s1 = fmaf(fv, __ldg(&a1[h * 16 + o]), s1);
          s2 = fmaf(fv, __ldg(&a2[h * 16 + o]), s2);
        }
        g_f1[(size_t)(row0 + r) * 8 + h] = s1;
        g_f2[(size_t)(row0 + r) * 8 + h] = s2;
      }
    }
    __syncthreads();  // Eh reads done before next A staging
  }
}

// ---------------------------------------------------------------------------
// agg: one warp per node. dst read as int4 (4-aligned after peel); batched
// 8-edge gathers (8 f2 + 8 feats in flight); all-lane exp (1 MUFU/edge).
// ---------------------------------------------------------------------------
__device__ __forceinline__ void agg_edge(int dj, float f1h, int lane,
                                         const uint2* fh, float4& acc, float& S) {
  float zj = f1h + __ldg(&g_f2[(size_t)dj * 8 + (lane >> 2)]);
  float wj = __expf(fmaxf(zj, 0.2f * zj));
  uint2 qj = __ldg(&fh[(size_t)dj * 32 + lane]);
  float2 fa = __half22float2(*reinterpret_cast<__half2*>(&qj.x));
  float2 fb = __half22float2(*reinterpret_cast<__half2*>(&qj.y));
  acc.x = fmaf(wj, fa.x, acc.x); acc.y = fmaf(wj, fa.y, acc.y);
  acc.z = fmaf(wj, fb.x, acc.z); acc.w = fmaf(wj, fb.y, acc.w);
  S += wj;
}

__global__ __launch_bounds__(256, 5) void agg_kernel(
    const int* __restrict__ dst, float* __restrict__ out, int n) {
  int warp = (blockIdx.x * 256 + threadIdx.x) >> 5;
  int lane = threadIdx.x & 31;
  if (warp >= n) return;
  const int node = warp;
  const int h4 = lane >> 2;

  const int start = g_rowptr[node];
  const int end   = g_rowptr[node + 1];
  const float f1h = g_f1[(size_t)node * 8 + h4];
  const uint2* fh = reinterpret_cast<const uint2*>(g_feats_h);

  float4 acc = make_float4(0.f, 0.f, 0.f, 0.f);
  float S = 0.f;

  int e = start;
  // peel to 4-alignment
  int lim = min(end, (start + 3) & ~3);
  for (; e < lim; e++) agg_edge(__ldg(&dst[e]), f1h, lane, fh, acc, S);

  // main: 8 edges per iter via two int4 dst loads
  for (; e + 8 <= end; e += 8) {
    int4 da = __ldg(reinterpret_cast<const int4*>(dst + e));
    int4 db = __ldg(reinterpret_cast<const int4*>(dst + e + 4));
    int d[8] = {da.x, da.y, da.z, da.w, db.x, db.y, db.z, db.w};
    float z[8];
#pragma unroll
    for (int j = 0; j < 8; j++) z[j] = f1h + __ldg(&g_f2[(size_t)d[j] * 8 + h4]);
    uint2 q[8];
#pragma unroll
    for (int j = 0; j < 8; j++) q[j] = __ldg(&fh[(size_t)d[j] * 32 + lane]);
#pragma unroll
    for (int j = 0; j < 8; j++) {
      float wj = __expf(fmaxf(z[j], 0.2f * z[j]));
      float2 fa = __half22float2(*reinterpret_cast<__half2*>(&q[j].x));
      float2 fb = __half22float2(*reinterpret_cast<__half2*>(&q[j].y));
      acc.x = fmaf(wj, fa.x, acc.x); acc.y = fmaf(wj, fa.y, acc.y);
      acc.z = fmaf(wj, fb.x, acc.z); acc.w = fmaf(wj, fb.y, acc.w);
      S += wj;
    }
  }
  // 4-edge quad if present
  if (e + 4 <= end) {
    int4 da = __ldg(reinterpret_cast<const int4*>(dst + e));
    agg_edge(da.x, f1h, lane, fh, acc, S);
    agg_edge(da.y, f1h, lane, fh, acc, S);
    agg_edge(da.z, f1h, lane, fh, acc, S);
    agg_edge(da.w, f1h, lane, fh, acc, S);
    e += 4;
  }
  for (; e < end; e++) agg_edge(__ldg(&dst[e]), f1h, lane, fh, acc, S);

  float4 o = make_float4(0.f, 0.f, 0.f, 0.f);
  if (end > start) {
    float inv = 1.f / S;
    o.x = acc.x * inv; o.y = acc.y * inv; o.z = acc.z * inv; o.w = acc.w * inv;
  }
  o.x = o.x > 0.f ? o.x : expm1f(o.x);
  o.y = o.y > 0.f ? o.y : expm1f(o.y);
  o.z = o.z > 0.f ? o.z : expm1f(o.z);
  o.w = o.w > 0.f ? o.w : expm1f(o.w);
  reinterpret_cast<float4*>(out)[(size_t)node * 32 + lane] = o;
}

// ---------------------------------------------------------------------------
extern "C" void kernel_launch(void* const* d_in, const int* in_sizes, int n_in,
                              void* d_out, int out_size) {
  const float* x  = (const float*)d_in[0];
  const float* W  = (const float*)d_in[1];
  const float* a1 = (const float*)d_in[2];
  const float* b1 = (const float*)d_in[3];
  const float* a2 = (const float*)d_in[4];
  const float* b2 = (const float*)d_in[5];
  const int*  src = (const int*)d_in[6];
  const int*  dst = (const int*)d_in[7];
  float* out = (float*)d_out;

  const int n = in_sizes[0] / 128;   // N
  const int e = in_sizes[6];         // E

  const int rp_blocks = (e + 1023) / 1024;           // 4 edges/thread
  const int n_tiles   = (n + 63) / 64;
  const int feat_ctas = (n_tiles < FEAT_CTAS) ? n_tiles : FEAT_CTAS;

  cudaFuncSetAttribute(feat_rp_kernel, cudaFuncAttributeMaxDynamicSharedMemorySize,
                       SMEM_FEAT_TOTAL);

  feat_rp_kernel<<<rp_blocks + feat_ctas, 256, SMEM_FEAT_TOTAL>>>(
      x, W, a1, b1, a2, b2, src, n, e, rp_blocks, n_tiles, feat_ctas);
  agg_kernel<<<(n + 7) / 8, 256>>>(dst, out, n);
}

// round 7
// speedup vs baseline: 2.2792x; 1.0927x over previous
#include <cuda_runtime.h>
#include <cuda_fp16.h>
#include <cstdint>

// Problem constants: N=100000, E=1600000, H=8, D_IN=128, D_HEAD=16
#define NMAX 100000
#define FEAT_CTAS 296   // 2 per SM on 148 SMs

// Scratch (allocation-free rule: __device__ globals)
__device__ __half g_feats_h[NMAX * 128];  // [N,128] fp16, 25.6 MB (L2-resident)
__device__ float  g_f1[NMAX * 8];
__device__ float  g_f2[NMAX * 8];
__device__ int    g_rowptr[NMAX + 1];

__device__ __forceinline__ uint32_t f2tf32(float f) {
  uint32_t u; asm("cvt.rna.tf32.f32 %0, %1;" : "=r"(u) : "f"(f)); return u;
}
__device__ __forceinline__ void mma_tf32(float c[4], uint32_t a0, uint32_t a1,
                                         uint32_t a2, uint32_t a3,
                                         uint32_t b0, uint32_t b1) {
  asm volatile(
      "mma.sync.aligned.m16n8k8.row.col.f32.tf32.tf32.f32 "
      "{%0,%1,%2,%3}, {%4,%5,%6,%7}, {%8,%9}, {%0,%1,%2,%3};"
      : "+f"(c[0]), "+f"(c[1]), "+f"(c[2]), "+f"(c[3])
      : "r"(a0), "r"(a1), "r"(a2), "r"(a3), "r"(b0), "r"(b1));
}

// ---------------------------------------------------------------------------
// Fused kernel: blocks [0, rp_blocks) build rowptr; the rest are persistent
// feat CTAs. B matrix = 144 cols: [0..127] = Wm (n = h*16+o),
// [128..135] = wa1[d,h], [136..143] = wa2[d,h]  (f1/f2 fused into GEMM).
// ---------------------------------------------------------------------------
#define AS_STRIDE 132
#define BS_STRIDE 152
#define EH_STRIDE 136
#define SMEM_FEAT_TOTAL ((64 * AS_STRIDE + 128 * BS_STRIDE) * 4)  // 111,616 B

__global__ __launch_bounds__(256, 2) void feat_rp_kernel(
    const float* __restrict__ x, const float* __restrict__ W,
    const float* __restrict__ a1, const float* __restrict__ b1,
    const float* __restrict__ a2, const float* __restrict__ b2,
    const int* __restrict__ src,
    int n, int e_total, int rp_blocks, int n_tiles, int feat_ctas) {
  extern __shared__ char smem[];
  const int tid = threadIdx.x;

  // ---------------- rowptr role ----------------
  if ((int)blockIdx.x < rp_blocks) {
    int base = (blockIdx.x * 256 + tid) * 4;
    if (base < e_total) {
      int cnt = min(4, e_total - base);
      int s[4];
      if (cnt == 4) {
        int4 s4 = *reinterpret_cast<const int4*>(&src[base]);
        s[0] = s4.x; s[1] = s4.y; s[2] = s4.z; s[3] = s4.w;
      } else {
        for (int j = 0; j < cnt; j++) s[j] = __ldg(&src[base + j]);
      }
      int prev = (base == 0) ? -1 : __ldg(&src[base - 1]);
      for (int j = 0; j < cnt; j++) {
        for (int v = prev + 1; v <= s[j]; v++) g_rowptr[v] = base + j;
        prev = s[j];
      }
      if (base + cnt == e_total)
        for (int v = prev + 1; v <= n; v++) g_rowptr[v] = e_total;
    }
    return;
  }

  // ---------------- persistent feat role ----------------
  uint32_t* As = reinterpret_cast<uint32_t*>(smem);
  uint32_t* Bs = As + 64 * AS_STRIDE;
  __half*   Eh = reinterpret_cast<__half*>(smem);   // overlays As between syncs

  const int f    = blockIdx.x - rp_blocks;
  const int w    = tid >> 5;
  const int lane = tid & 31;
  const int qid  = lane >> 2;     // 0..7
  const int tq   = lane & 3;      // 0..3
  const int rw   = (w & 3) * 16;  // warp row base
  const int cb   = (w >> 2) * 72; // warp col base (0 or 72)

  // Stage B once: Bs[k=d][c=h*16+o] = W[h][d][o] (tf32-rounded)
  for (int i = tid; i < 4096; i += 256) {
    int h = i >> 9, d = (i >> 2) & 127, o0 = (i & 3) * 4;
    float4 v = *reinterpret_cast<const float4*>(&W[(size_t)h * 2048 + d * 16 + o0]);
    uint4 u = make_uint4(f2tf32(v.x), f2tf32(v.y), f2tf32(v.z), f2tf32(v.w));
    *reinterpret_cast<uint4*>(&Bs[d * BS_STRIDE + h * 16 + o0]) = u;
  }
  // wa1/wa2 columns: Bs[d][128+h] = sum_o W[h][d][o]*a1[h][o], [136+h] for a2
  for (int i = tid; i < 1024; i += 256) {
    int d = i >> 3, h = i & 7;
    float s1 = 0.f, s2 = 0.f;
#pragma unroll
    for (int o = 0; o < 16; o++) {
      float wv = __ldg(&W[(size_t)h * 2048 + d * 16 + o]);
      s1 = fmaf(wv, __ldg(&a1[h * 16 + o]), s1);
      s2 = fmaf(wv, __ldg(&a2[h * 16 + o]), s2);
    }
    Bs[d * BS_STRIDE + 128 + h] = f2tf32(s1);
    Bs[d * BS_STRIDE + 136 + h] = f2tf32(s2);
  }
  const float b1a = __ldg(&b1[0]);  // biases are per-head; load lazily below
  (void)b1a;

  for (int t = f; t < n_tiles; t += feat_ctas) {
    const int row0 = t * 64;
    const int nrows = min(64, n - row0);

    // Stage A tile (tf32-rounded), zero-fill OOB rows
    for (int i = tid; i < 2048; i += 256) {
      int r = i >> 5, k4 = i & 31;
      float4 v = make_float4(0.f, 0.f, 0.f, 0.f);
      if (r < nrows) v = reinterpret_cast<const float4*>(x)[(size_t)(row0 + r) * 32 + k4];
      uint4 u = make_uint4(f2tf32(v.x), f2tf32(v.y), f2tf32(v.z), f2tf32(v.w));
      *reinterpret_cast<uint4*>(&As[r * AS_STRIDE + k4 * 4]) = u;
    }
    __syncthreads();

    float c[9][4];
#pragma unroll
    for (int nt = 0; nt < 9; nt++)
#pragma unroll
      for (int j = 0; j < 4; j++) c[nt][j] = 0.f;

    const uint32_t* Abase = &As[(rw + qid) * AS_STRIDE + tq];
#pragma unroll 4
    for (int ks = 0; ks < 16; ks++) {
      const int k0 = ks * 8;
      uint32_t a0 = Abase[k0];
      uint32_t a2r = Abase[k0 + 4];
      uint32_t a1r = Abase[k0 + 8 * AS_STRIDE];
      uint32_t a3 = Abase[k0 + 8 * AS_STRIDE + 4];
      const uint32_t* B0 = &Bs[(k0 + tq) * BS_STRIDE + cb + qid];
      const uint32_t* B1 = B0 + 4 * BS_STRIDE;
#pragma unroll
      for (int nt = 0; nt < 9; nt++)
        mma_tf32(c[nt], a0, a1r, a2r, a3, B0[nt * 8], B1[nt * 8]);
    }
    __syncthreads();  // MMA reads of As done; overlay Eh

    // Fragments -> Eh (feats cols) or direct f1/f2 stores (cols >= 128)
    {
      const int r0 = rw + qid;
      const int grow0 = row0 + r0;
#pragma unroll
      for (int nt = 0; nt < 9; nt++) {
        int col = cb + nt * 8 + tq * 2;
        if (col < 128) {
          *reinterpret_cast<__half2*>(&Eh[r0 * EH_STRIDE + col]) =
              __floats2half2_rn(c[nt][0], c[nt][1]);
          *reinterpret_cast<__half2*>(&Eh[(r0 + 8) * EH_STRIDE + col]) =
              __floats2half2_rn(c[nt][2], c[nt][3]);
        } else if (col < 136) {
          int h = col - 128;
          float bh0 = __ldg(&b1[h]), bh1 = __ldg(&b1[h + 1]);
          if (grow0 < n) {
            g_f1[(size_t)grow0 * 8 + h]     = c[nt][0] + bh0;
            g_f1[(size_t)grow0 * 8 + h + 1] = c[nt][1] + bh1;
          }
          if (grow0 + 8 < n) {
            g_f1[(size_t)(grow0 + 8) * 8 + h]     = c[nt][2] + bh0;
            g_f1[(size_t)(grow0 + 8) * 8 + h + 1] = c[nt][3] + bh1;
          }
        } else {
          int h = col - 136;
          float bh0 = __ldg(&b2[h]), bh1 = __ldg(&b2[h + 1]);
          if (grow0 < n) {
            g_f2[(size_t)grow0 * 8 + h]     = c[nt][0] + bh0;
            g_f2[(size_t)grow0 * 8 + h + 1] = c[nt][1] + bh1;
          }
          if (grow0 + 8 < n) {
            g_f2[(size_t)(grow0 + 8) * 8 + h]     = c[nt][2] + bh0;
            g_f2[(size_t)(grow0 + 8) * 8 + h + 1] = c[nt][3] + bh1;
          }
        }
      }
    }
    __syncthreads();

    // Coalesced feats store: 64 rows x 16 uint4
    for (int task = tid; task < 1024; task += 256) {
      int r = task >> 4, seg = task & 15;
      if (r < nrows)
        *reinterpret_cast<uint4*>(&g_feats_h[(size_t)(row0 + r) * 128 + seg * 8]) =
            *reinterpret_cast<const uint4*>(&Eh[r * EH_STRIDE + seg * 8]);
    }
    __syncthreads();  // Eh reads done before next A staging
  }
}

// ---------------------------------------------------------------------------
// agg: one warp per node, EDGE-PAIRED: lanes split p = lane>>4 (edge parity),
// g = lane&15 (8-dim group, head g>>1). Per 2 edges per lane:
// 1 uint4 feats LDG + 1 f2 LDG + 1 exp. Halves combined via shfl_xor(16).
// ---------------------------------------------------------------------------
__global__ __launch_bounds__(256, 5) void agg_kernel(
    const int* __restrict__ dst, float* __restrict__ out, int n) {
  int warp = (blockIdx.x * 256 + threadIdx.x) >> 5;
  int lane = threadIdx.x & 31;
  if (warp >= n) return;
  const int node = warp;
  const int p  = lane >> 4;   // edge parity
  const int g  = lane & 15;   // dim group: dims 8g..8g+7
  const int hg = g >> 1;      // head of this dim group

  const int start = g_rowptr[node];
  const int end   = g_rowptr[node + 1];
  const float f1h = g_f1[(size_t)node * 8 + hg];
  const uint4* fh4 = reinterpret_cast<const uint4*>(g_feats_h);

  float acc[8];
#pragma unroll
  for (int k = 0; k < 8; k++) acc[k] = 0.f;
  float S = 0.f;

  int e = start;
  for (; e + 8 <= end; e += 8) {
    int dp[4];
#pragma unroll
    for (int j = 0; j < 4; j++) dp[j] = __ldg(&dst[e + 2 * j + p]);
    float z[4];
#pragma unroll
    for (int j = 0; j < 4; j++) z[j] = f1h + __ldg(&g_f2[(size_t)dp[j] * 8 + hg]);
    uint4 q[4];
#pragma unroll
    for (int j = 0; j < 4; j++) q[j] = __ldg(&fh4[(size_t)dp[j] * 16 + g]);
#pragma unroll
    for (int j = 0; j < 4; j++) {
      float wj = __expf(fmaxf(z[j], 0.2f * z[j]));
      float2 f0 = __half22float2(*reinterpret_cast<__half2*>(&q[j].x));
      float2 f1v = __half22float2(*reinterpret_cast<__half2*>(&q[j].y));
      float2 f2v = __half22float2(*reinterpret_cast<__half2*>(&q[j].z));
      float2 f3 = __half22float2(*reinterpret_cast<__half2*>(&q[j].w));
      acc[0] = fmaf(wj, f0.x, acc[0]); acc[1] = fmaf(wj, f0.y, acc[1]);
      acc[2] = fmaf(wj, f1v.x, acc[2]); acc[3] = fmaf(wj, f1v.y, acc[3]);
      acc[4] = fmaf(wj, f2v.x, acc[4]); acc[5] = fmaf(wj, f2v.y, acc[5]);
      acc[6] = fmaf(wj, f3.x, acc[6]); acc[7] = fmaf(wj, f3.y, acc[7]);
      S += wj;
    }
  }
  // tail: pairs (possibly final single edge)
  for (; e < end; e += 2) {
    int dj = -1;
    if (p == 0) dj = __ldg(&dst[e]);
    else if (e + 1 < end) dj = __ldg(&dst[e + 1]);
    if (dj >= 0) {
      float zj = f1h + __ldg(&g_f2[(size_t)dj * 8 + hg]);
      float wj = __expf(fmaxf(zj, 0.2f * zj));
      uint4 qj = __ldg(&fh4[(size_t)dj * 16 + g]);
      float2 f0 = __half22float2(*reinterpret_cast<__half2*>(&qj.x));
      float2 f1v = __half22float2(*reinterpret_cast<__half2*>(&qj.y));
      float2 f2v = __half22float2(*reinterpret_cast<__half2*>(&qj.z));
      float2 f3 = __half22float2(*reinterpret_cast<__half2*>(&qj.w));
      acc[0] = fmaf(wj, f0.x, acc[0]); acc[1] = fmaf(wj, f0.y, acc[1]);
      acc[2] = fmaf(wj, f1v.x, acc[2]); acc[3] = fmaf(wj, f1v.y, acc[3]);
      acc[4] = fmaf(wj, f2v.x, acc[4]); acc[5] = fmaf(wj, f2v.y, acc[5]);
      acc[6] = fmaf(wj, f3.x, acc[6]); acc[7] = fmaf(wj, f3.y, acc[7]);
      S += wj;
    }
  }

  // combine the two edge-parity halves (lane <-> lane^16 hold same dims)
  S += __shfl_xor_sync(0xffffffffu, S, 16);
#pragma unroll
  for (int k = 0; k < 8; k++) acc[k] += __shfl_xor_sync(0xffffffffu, acc[k], 16);

  float inv = (end > start) ? (1.f / S) : 0.f;
  // lane writes its half: p=0 -> dims 8g..8g+3, p=1 -> dims 8g+4..8g+7
  const int base = p * 4;
  float4 o;
  o.x = acc[base + 0] * inv; o.y = acc[base + 1] * inv;
  o.z = acc[base + 2] * inv; o.w = acc[base + 3] * inv;
  o.x = o.x > 0.f ? o.x : expm1f(o.x);
  o.y = o.y > 0.f ? o.y : expm1f(o.y);
  o.z = o.z > 0.f ? o.z : expm1f(o.z);
  o.w = o.w > 0.f ? o.w : expm1f(o.w);
  reinterpret_cast<float4*>(out)[(size_t)node * 32 + g * 2 + p] = o;
}

// ---------------------------------------------------------------------------
extern "C" void kernel_launch(void* const* d_in, const int* in_sizes, int n_in,
                              void* d_out, int out_size) {
  const float* x  = (const float*)d_in[0];
  const float* W  = (const float*)d_in[1];
  const float* a1 = (const float*)d_in[2];
  const float* b1 = (const float*)d_in[3];
  const float* a2 = (const float*)d_in[4];
  const float* b2 = (const float*)d_in[5];
  const int*  src = (const int*)d_in[6];
  const int*  dst = (const int*)d_in[7];
  float* out = (float*)d_out;

  const int n = in_sizes[0] / 128;   // N
  const int e = in_sizes[6];         // E

  const int rp_blocks = (e + 1023) / 1024;           // 4 edges/thread
  const int n_tiles   = (n + 63) / 64;
  const int feat_ctas = (n_tiles < FEAT_CTAS) ? n_tiles : FEAT_CTAS;

  cudaFuncSetAttribute(feat_rp_kernel, cudaFuncAttributeMaxDynamicSharedMemorySize,
                       SMEM_FEAT_TOTAL);

  feat_rp_kernel<<<rp_blocks + feat_ctas, 256, SMEM_FEAT_TOTAL>>>(
      x, W, a1, b1, a2, b2, src, n, e, rp_blocks, n_tiles, feat_ctas);
  agg_kernel<<<(n + 7) / 8, 256>>>(dst, out, n);
}

// round 8
// speedup vs baseline: 2.4228x; 1.0630x over previous
#include <cuda_runtime.h>
#include <cuda_fp16.h>
#include <cstdint>

// Problem constants: N=100000, E=1600000, H=8, D_IN=128, D_HEAD=16
#define NMAX 100000
#define FEAT_CTAS 296   // 2 per SM on 148 SMs
#define AGG_BLOCKS 592  // persistent agg blocks (4 per SM target)

// Scratch (allocation-free rule: __device__ globals)
__device__ __half g_feats_h[NMAX * 128];  // [N,128] fp16, 25.6 MB (L2-resident)
__device__ float  g_f1[NMAX * 8];
__device__ float  g_f2[NMAX * 8];
__device__ int    g_rowptr[NMAX + 1];
__device__ int    g_ctr;                  // persistent-agg work counter

__device__ __forceinline__ void mma_f16(float c[4], uint32_t a0, uint32_t a1,
                                        uint32_t a2, uint32_t a3,
                                        uint32_t b0, uint32_t b1) {
  asm volatile(
      "mma.sync.aligned.m16n8k16.row.col.f32.f16.f16.f32 "
      "{%0,%1,%2,%3}, {%4,%5,%6,%7}, {%8,%9}, {%0,%1,%2,%3};"
      : "+f"(c[0]), "+f"(c[1]), "+f"(c[2]), "+f"(c[3])
      : "r"(a0), "r"(a1), "r"(a2), "r"(a3), "r"(b0), "r"(b1));
}

// ---------------------------------------------------------------------------
// Fused kernel: blocks [0, rp_blocks) build rowptr (+ reset g_ctr);
// the rest are persistent feat CTAs running fp16 MMA.
// B = 144 cols (halves): [0..127] = Wm (n=h*16+o), [128..135] = wa1[d,h],
// [136..143] = wa2[d,h] (f1/f2 fused into the GEMM).
// Smem halves, stride 136 (272B rows): A 64x136, B 144x136. Eh overlays A.
// ---------------------------------------------------------------------------
#define ASH 136   // A stride in halves (68 words)
#define BSH 136   // B stride in halves
#define EHS 136   // Eh stride in halves
#define SMEM_FEAT_TOTAL ((64 * ASH + 144 * BSH) * 2)  // 56,576 B

__global__ __launch_bounds__(256, 2) void feat_rp_kernel(
    const float* __restrict__ x, const float* __restrict__ W,
    const float* __restrict__ a1, const float* __restrict__ b1,
    const float* __restrict__ a2, const float* __restrict__ b2,
    const int* __restrict__ src,
    int n, int e_total, int rp_blocks, int n_tiles, int feat_ctas) {
  extern __shared__ char smem[];
  const int tid = threadIdx.x;

  // ---------------- rowptr role ----------------
  if ((int)blockIdx.x < rp_blocks) {
    if (blockIdx.x == 0 && tid == 0) g_ctr = 0;   // reset agg work counter
    int base = (blockIdx.x * 256 + tid) * 4;
    if (base < e_total) {
      int cnt = min(4, e_total - base);
      int s[4];
      if (cnt == 4) {
        int4 s4 = *reinterpret_cast<const int4*>(&src[base]);
        s[0] = s4.x; s[1] = s4.y; s[2] = s4.z; s[3] = s4.w;
      } else {
        for (int j = 0; j < cnt; j++) s[j] = __ldg(&src[base + j]);
      }
      int prev = (base == 0) ? -1 : __ldg(&src[base - 1]);
      for (int j = 0; j < cnt; j++) {
        for (int v = prev + 1; v <= s[j]; v++) g_rowptr[v] = base + j;
        prev = s[j];
      }
      if (base + cnt == e_total)
        for (int v = prev + 1; v <= n; v++) g_rowptr[v] = e_total;
    }
    return;
  }

  // ---------------- persistent feat role ----------------
  __half* Ah = reinterpret_cast<__half*>(smem);
  __half* Bh = Ah + 64 * ASH;
  __half* Eh = Ah;                               // overlays A between syncs
  const uint32_t* A32 = reinterpret_cast<const uint32_t*>(Ah);
  const uint32_t* B32 = reinterpret_cast<const uint32_t*>(Bh);

  const int f    = blockIdx.x - rp_blocks;
  const int w    = tid >> 5;
  const int lane = tid & 31;
  const int qid  = lane >> 2;     // 0..7
  const int tq   = lane & 3;      // 0..3
  const int rw   = (w & 3) * 16;  // warp row base
  const int cb   = (w >> 2) * 72; // warp col base (0 or 72)

  // Stage B once: Bh[c=h*16+o][d] = half(W[h][d][o])
  for (int i = tid; i < 4096; i += 256) {
    int h = i >> 9, d = (i >> 2) & 127, o0 = (i & 3) * 4;
    float4 v = *reinterpret_cast<const float4*>(&W[(size_t)h * 2048 + d * 16 + o0]);
    int c0 = h * 16 + o0;
    Bh[(c0 + 0) * BSH + d] = __float2half_rn(v.x);
    Bh[(c0 + 1) * BSH + d] = __float2half_rn(v.y);
    Bh[(c0 + 2) * BSH + d] = __float2half_rn(v.z);
    Bh[(c0 + 3) * BSH + d] = __float2half_rn(v.w);
  }
  // wa1/wa2 columns: Bh[128+h][d], Bh[136+h][d]
  for (int i = tid; i < 1024; i += 256) {
    int d = i >> 3, h = i & 7;
    float s1 = 0.f, s2 = 0.f;
#pragma unroll
    for (int o = 0; o < 16; o++) {
      float wv = __ldg(&W[(size_t)h * 2048 + d * 16 + o]);
      s1 = fmaf(wv, __ldg(&a1[h * 16 + o]), s1);
      s2 = fmaf(wv, __ldg(&a2[h * 16 + o]), s2);
    }
    Bh[(128 + h) * BSH + d] = __float2half_rn(s1);
    Bh[(136 + h) * BSH + d] = __float2half_rn(s2);
  }

  for (int t = f; t < n_tiles; t += feat_ctas) {
    const int row0 = t * 64;
    const int nrows = min(64, n - row0);

    // Stage A tile: x float4 -> 4 halves (uint2 store)
    for (int i = tid; i < 2048; i += 256) {
      int r = i >> 5, k4 = i & 31;
      float4 v = make_float4(0.f, 0.f, 0.f, 0.f);
      if (r < nrows) v = reinterpret_cast<const float4*>(x)[(size_t)(row0 + r) * 32 + k4];
      __half2 h0 = __floats2half2_rn(v.x, v.y);
      __half2 h1 = __floats2half2_rn(v.z, v.w);
      uint2 u = make_uint2(*reinterpret_cast<uint32_t*>(&h0),
                           *reinterpret_cast<uint32_t*>(&h1));
      *reinterpret_cast<uint2*>(&Ah[r * ASH + k4 * 4]) = u;
    }
    __syncthreads();

    float c[9][4];
#pragma unroll
    for (int nt = 0; nt < 9; nt++)
#pragma unroll
      for (int j = 0; j < 4; j++) c[nt][j] = 0.f;

    const int arow = (rw + qid) * (ASH / 2) + tq;   // word index
#pragma unroll
    for (int ks = 0; ks < 8; ks++) {
      const int kw = ks * 8;
      uint32_t a0 = A32[arow + kw];
      uint32_t a2 = A32[arow + kw + 4];
      uint32_t a1 = A32[arow + kw + 8 * (ASH / 2)];
      uint32_t a3 = A32[arow + kw + 8 * (ASH / 2) + 4];
      const uint32_t* Bp = &B32[(cb + qid) * (BSH / 2) + kw + tq];
#pragma unroll
      for (int nt = 0; nt < 9; nt++)
        mma_f16(c[nt], a0, a1, a2, a3, Bp[nt * 8 * (BSH / 2)], Bp[nt * 8 * (BSH / 2) + 4]);
    }
    __syncthreads();  // MMA reads of A done; overlay Eh

    // Fragments -> Eh (feats cols) or direct f1/f2 stores (cols >= 128)
    {
      const int r0 = rw + qid;
      const int grow0 = row0 + r0;
#pragma unroll
      for (int nt = 0; nt < 9; nt++) {
        int col = cb + nt * 8 + tq * 2;
        if (col < 128) {
          *reinterpret_cast<__half2*>(&Eh[r0 * EHS + col]) =
              __floats2half2_rn(c[nt][0], c[nt][1]);
          *reinterpret_cast<__half2*>(&Eh[(r0 + 8) * EHS + col]) =
              __floats2half2_rn(c[nt][2], c[nt][3]);
        } else if (col < 136) {
          int h = col - 128;
          float bh0 = __ldg(&b1[h]), bh1 = __ldg(&b1[h + 1]);
          if (grow0 < n) {
            g_f1[(size_t)grow0 * 8 + h]     = c[nt][0] + bh0;
            g_f1[(size_t)grow0 * 8 + h + 1] = c[nt][1] + bh1;
          }
          if (grow0 + 8 < n) {
            g_f1[(size_t)(grow0 + 8) * 8 + h]     = c[nt][2] + bh0;
            g_f1[(size_t)(grow0 + 8) * 8 + h + 1] = c[nt][3] + bh1;
          }
        } else {
          int h = col - 136;
          float bh0 = __ldg(&b2[h]), bh1 = __ldg(&b2[h + 1]);
          if (grow0 < n) {
            g_f2[(size_t)grow0 * 8 + h]     = c[nt][0] + bh0;
            g_f2[(size_t)grow0 * 8 + h + 1] = c[nt][1] + bh1;
          }
          if (grow0 + 8 < n) {
            g_f2[(size_t)(grow0 + 8) * 8 + h]     = c[nt][2] + bh0;
            g_f2[(size_t)(grow0 + 8) * 8 + h + 1] = c[nt][3] + bh1;
          }
        }
      }
    }
    __syncthreads();

    // Coalesced feats store: 64 rows x 16 uint4
    for (int task = tid; task < 1024; task += 256) {
      int r = task >> 4, seg = task & 15;
      if (r < nrows)
        *reinterpret_cast<uint4*>(&g_feats_h[(size_t)(row0 + r) * 128 + seg * 8]) =
            *reinterpret_cast<const uint4*>(&Eh[r * EHS + seg * 8]);
    }
    __syncthreads();  // Eh reads done before next A staging
  }
}

// ---------------------------------------------------------------------------
// agg: persistent warps, atomic work counter (2 nodes/fetch) for warp-level
// load balance. Edge-paired lanes: p = lane>>4 (edge parity), g = lane&15
// (8-dim group, head g>>1). Per 2 edges per lane: 1 uint4 feats LDG +
// 1 f2 LDG + 1 exp. Halves combined via shfl_xor(16).
// ---------------------------------------------------------------------------
__device__ __forceinline__ void agg_node(
    int node, int lane, int p, int g, int hg,
    const int* __restrict__ dst, const uint4* __restrict__ fh4,
    float* __restrict__ out) {
  const int start = g_rowptr[node];
  const int end   = g_rowptr[node + 1];
  const float f1h = g_f1[(size_t)node * 8 + hg];

  float acc[8];
#pragma unroll
  for (int k = 0; k < 8; k++) acc[k] = 0.f;
  float S = 0.f;

  int e = start;
  for (; e + 8 <= end; e += 8) {
    int dp[4];
#pragma unroll
    for (int j = 0; j < 4; j++) dp[j] = __ldg(&dst[e + 2 * j + p]);
    float z[4];
#pragma unroll
    for (int j = 0; j < 4; j++) z[j] = f1h + __ldg(&g_f2[(size_t)dp[j] * 8 + hg]);
    uint4 q[4];
#pragma unroll
    for (int j = 0; j < 4; j++) q[j] = __ldg(&fh4[(size_t)dp[j] * 16 + g]);
#pragma unroll
    for (int j = 0; j < 4; j++) {
      float wj = __expf(fmaxf(z[j], 0.2f * z[j]));
      float2 f0 = __half22float2(*reinterpret_cast<__half2*>(&q[j].x));
      float2 f1v = __half22float2(*reinterpret_cast<__half2*>(&q[j].y));
      float2 f2v = __half22float2(*reinterpret_cast<__half2*>(&q[j].z));
      float2 f3 = __half22float2(*reinterpret_cast<__half2*>(&q[j].w));
      acc[0] = fmaf(wj, f0.x, acc[0]); acc[1] = fmaf(wj, f0.y, acc[1]);
      acc[2] = fmaf(wj, f1v.x, acc[2]); acc[3] = fmaf(wj, f1v.y, acc[3]);
      acc[4] = fmaf(wj, f2v.x, acc[4]); acc[5] = fmaf(wj, f2v.y, acc[5]);
      acc[6] = fmaf(wj, f3.x, acc[6]); acc[7] = fmaf(wj, f3.y, acc[7]);
      S += wj;
    }
  }
  for (; e < end; e += 2) {
    int dj = -1;
    if (p == 0) dj = __ldg(&dst[e]);
    else if (e + 1 < end) dj = __ldg(&dst[e + 1]);
    if (dj >= 0) {
      float zj = f1h + __ldg(&g_f2[(size_t)dj * 8 + hg]);
      float wj = __expf(fmaxf(zj, 0.2f * zj));
      uint4 qj = __ldg(&fh4[(size_t)dj * 16 + g]);
      float2 f0 = __half22float2(*reinterpret_cast<__half2*>(&qj.x));
      float2 f1v = __half22float2(*reinterpret_cast<__half2*>(&qj.y));
      float2 f2v = __half22float2(*reinterpret_cast<__half2*>(&qj.z));
      float2 f3 = __half22float2(*reinterpret_cast<__half2*>(&qj.w));
      acc[0] = fmaf(wj, f0.x, acc[0]); acc[1] = fmaf(wj, f0.y, acc[1]);
      acc[2] = fmaf(wj, f1v.x, acc[2]); acc[3] = fmaf(wj, f1v.y, acc[3]);
      acc[4] = fmaf(wj, f2v.x, acc[4]); acc[5] = fmaf(wj, f2v.y, acc[5]);
      acc[6] = fmaf(wj, f3.x, acc[6]); acc[7] = fmaf(wj, f3.y, acc[7]);
      S += wj;
    }
  }

  S += __shfl_xor_sync(0xffffffffu, S, 16);
#pragma unroll
  for (int k = 0; k < 8; k++) acc[k] += __shfl_xor_sync(0xffffffffu, acc[k], 16);

  float inv = (end > start) ? (1.f / S) : 0.f;
  const int base = p * 4;
  float4 o;
  o.x = acc[base + 0] * inv; o.y = acc[base + 1] * inv;
  o.z = acc[base + 2] * inv; o.w = acc[base + 3] * inv;
  o.x = o.x > 0.f ? o.x : expm1f(o.x);
  o.y = o.y > 0.f ? o.y : expm1f(o.y);
  o.z = o.z > 0.f ? o.z : expm1f(o.z);
  o.w = o.w > 0.f ? o.w : expm1f(o.w);
  reinterpret_cast<float4*>(out)[(size_t)node * 32 + g * 2 + p] = o;
}

__global__ __launch_bounds__(256, 4) void agg_kernel(
    const int* __restrict__ dst, float* __restrict__ out, int n) {
  const int lane = threadIdx.x & 31;
  const int p  = lane >> 4;
  const int g  = lane & 15;
  const int hg = g >> 1;
  const uint4* fh4 = reinterpret_cast<const uint4*>(g_feats_h);

  for (;;) {
    int base = 0;
    if (lane == 0) base = atomicAdd(&g_ctr, 2);
    base = __shfl_sync(0xffffffffu, base, 0);
    if (base >= n) break;
    agg_node(base, lane, p, g, hg, dst, fh4, out);
    if (base + 1 < n) agg_node(base + 1, lane, p, g, hg, dst, fh4, out);
  }
}

// ---------------------------------------------------------------------------
extern "C" void kernel_launch(void* const* d_in, const int* in_sizes, int n_in,
                              void* d_out, int out_size) {
  const float* x  = (const float*)d_in[0];
  const float* W  = (const float*)d_in[1];
  const float* a1 = (const float*)d_in[2];
  const float* b1 = (const float*)d_in[3];
  const float* a2 = (const float*)d_in[4];
  const float* b2 = (const float*)d_in[5];
  const int*  src = (const int*)d_in[6];
  const int*  dst = (const int*)d_in[7];
  float* out = (float*)d_out;

  const int n = in_sizes[0] / 128;   // N
  const int e = in_sizes[6];         // E

  const int rp_blocks = (e + 1023) / 1024;           // 4 edges/thread
  const int n_tiles   = (n + 63) / 64;
  const int feat_ctas = (n_tiles < FEAT_CTAS) ? n_tiles : FEAT_CTAS;

  cudaFuncSetAttribute(feat_rp_kernel, cudaFuncAttributeMaxDynamicSharedMemorySize,
                       SMEM_FEAT_TOTAL);

  feat_rp_kernel<<<rp_blocks + feat_ctas, 256, SMEM_FEAT_TOTAL>>>(
      x, W, a1, b1, a2, b2, src, n, e, rp_blocks, n_tiles, feat_ctas);
  agg_kernel<<<AGG_BLOCKS, 256>>>(dst, out, n);
}